// round 1
// baseline (speedup 1.0000x reference)
#include <cuda_runtime.h>
#include <math.h>

// ---------------- problem constants ----------------
#define Bn   128
#define Pn   196
#define ENCn 2048
#define DECn 512
#define ATTn 512
#define EMBn 512
#define Vn   10000
#define Tn   30
#define TMn  29   // T-1 decode steps

// ---------------- output layout (float32, tuple flattened in order) ----------------
// (caps[128,30], len_dec[128], predictions[128,29,10000], alphas[128,29,196], order[128])
#define OFF_CAPS  0ull
#define OFF_LEN   (128ull*30)
#define OFF_PRED  (OFF_LEN + 128ull)
#define OFF_ALPHA (OFF_PRED + 128ull*29*10000)
#define OFF_ORDER (OFF_ALPHA + 128ull*29*196)

// ---------------- device scratch (statics; no allocation in kernel_launch) ----------------
__device__ int   g_order[Bn];
__device__ int   g_lendec[Bn];
__device__ int   g_caps[Bn*Tn];
__device__ int   g_rowmap[Bn*Pn];
__device__ float g_part[8*128*2048];          // split-K partials (max S*M*N)
__device__ float g_scratch[14443008];         // see offsets below

// scratch offsets (floats)
#define S_ATTENC   0ull                       // 25088*512
#define S_MU       12845056ull                // 128*2048
#define S_H        13107200ull                // 128*512
#define S_C        13172736ull
#define S_ATTDEC   13238272ull
#define S_ALPHA    13303808ull                // 128*196
#define S_WEIGHT   13328896ull                // 128*2048
#define S_GATE     13591040ull                // 128*2048
#define S_X1       13853184ull                // 128*2560
#define S_GATES    14180864ull                // 128*2048

__device__ __forceinline__ float sigf(float x) { return 1.0f / (1.0f + expf(-x)); }

// ---------------- sort (stable counting sort, descending lens) ----------------
__global__ void k_sort(const int* __restrict__ lenc, const int* __restrict__ caps,
                       float* __restrict__ out)
{
    __shared__ int so[Bn];
    int tid = threadIdx.x;
    if (tid == 0) {
        int idx = 0;
        for (int v = Tn; v >= 2; --v)
            for (int b = 0; b < Bn; ++b)
                if (lenc[b] == v) so[idx++] = b;
    }
    __syncthreads();
    int ob = so[tid];
    g_order[tid]  = ob;
    int L = lenc[ob];
    g_lendec[tid] = L - 1;
    out[OFF_LEN   + tid] = (float)(L - 1);
    out[OFF_ORDER + tid] = (float)ob;
    for (int t = 0; t < Tn; ++t) {
        int cv = caps[ob * Tn + t];
        g_caps[tid * Tn + t] = cv;
        out[OFF_CAPS + (size_t)tid * Tn + t] = (float)cv;
    }
    for (int p = 0; p < Pn; ++p)
        g_rowmap[tid * Pn + p] = ob * Pn + p;
}

// ---------------- mu = mean over P of enc[order[b]] ----------------
__global__ void k_mu(const float* __restrict__ enc, float* __restrict__ mu)
{
    int b = blockIdx.x;
    int ob = g_order[b];
    const float* e = enc + (size_t)ob * Pn * ENCn;
    for (int d = threadIdx.x; d < ENCn; d += blockDim.x) {
        float s = 0.f;
        for (int p = 0; p < Pn; ++p) s += e[(size_t)p * ENCn + d];
        mu[(size_t)b * ENCn + d] = s * (1.0f / 196.0f);
    }
}

// ---------------- generic SGEMM: C[M,N] = A[M,K] @ B[N,K]^T (+bias) ----------------
// grid (ceil(N/64), M/64, S). S>1 -> write split-K partials to g_part (no bias).
// mode==1 : masked store into predictions output layout.
__global__ void __launch_bounds__(256) k_sgemm(
    const float* __restrict__ A, const float* __restrict__ B,
    float* __restrict__ C, const float* __restrict__ bias,
    int M, int N, int K, int S, int gatherA, int mode, int tstep)
{
    const int BM = 64, BN = 64, BK = 16;
    __shared__ float As[BK][BM + 4];
    __shared__ float Bs[BK][BN + 4];

    int tid = threadIdx.x;
    int n0 = blockIdx.x * BN, m0 = blockIdx.y * BM;
    int Kc = K / S;
    int k0 = blockIdx.z * Kc, kend = k0 + Kc;

    int a_m = tid >> 2, a_k = (tid & 3) << 2;
    int arow = m0 + a_m;
    int asrcrow = gatherA ? g_rowmap[arow] : arow;
    const float* Ap = A + (size_t)asrcrow * K;

    int b_n = tid >> 2, b_k = (tid & 3) << 2;
    int brow = n0 + b_n;
    bool bval = brow < N;
    const float* Bp = B + (size_t)(bval ? brow : 0) * K;

    int ty = tid >> 4, tx = tid & 15;
    float acc[4][4] = {};

    for (int kk = k0; kk < kend; kk += BK) {
        float4 av = *(const float4*)(Ap + kk + a_k);
        float4 bv = bval ? *(const float4*)(Bp + kk + b_k)
                         : make_float4(0.f, 0.f, 0.f, 0.f);
        __syncthreads();
        As[a_k + 0][a_m] = av.x; As[a_k + 1][a_m] = av.y;
        As[a_k + 2][a_m] = av.z; As[a_k + 3][a_m] = av.w;
        Bs[b_k + 0][b_n] = bv.x; Bs[b_k + 1][b_n] = bv.y;
        Bs[b_k + 2][b_n] = bv.z; Bs[b_k + 3][b_n] = bv.w;
        __syncthreads();
#pragma unroll
        for (int k = 0; k < BK; ++k) {
            float4 a4 = *(const float4*)(&As[k][ty << 2]);
            float4 b4 = *(const float4*)(&Bs[k][tx << 2]);
            float ar[4] = {a4.x, a4.y, a4.z, a4.w};
            float br[4] = {b4.x, b4.y, b4.z, b4.w};
#pragma unroll
            for (int i = 0; i < 4; ++i)
#pragma unroll
                for (int j = 0; j < 4; ++j)
                    acc[i][j] = fmaf(ar[i], br[j], acc[i][j]);
        }
    }

    if (S > 1) {
        float* P = g_part + (size_t)blockIdx.z * M * N;
#pragma unroll
        for (int i = 0; i < 4; ++i) {
            int row = m0 + (ty << 2) + i;
#pragma unroll
            for (int j = 0; j < 4; ++j) {
                int col = n0 + (tx << 2) + j;
                if (col < N) P[(size_t)row * N + col] = acc[i][j];
            }
        }
    } else {
#pragma unroll
        for (int i = 0; i < 4; ++i) {
            int row = m0 + (ty << 2) + i;
#pragma unroll
            for (int j = 0; j < 4; ++j) {
                int col = n0 + (tx << 2) + j;
                if (col >= N) continue;
                float v = acc[i][j] + (bias ? bias[col] : 0.f);
                if (mode == 1) {
                    int msk = tstep < g_lendec[row];
                    C[((size_t)row * TMn + tstep) * Vn + col] = msk ? v : 0.f;
                } else {
                    C[(size_t)row * N + col] = v;
                }
            }
        }
    }
}

// ---------------- split-K reduce: C = (sum_z part) + b1 + b2, optional sigmoid/acc ----------------
__global__ void k_reduce(float* __restrict__ C, const float* __restrict__ b1,
                         const float* __restrict__ b2,
                         int MN, int N, int S, int act, int accf)
{
    int i = blockIdx.x * 256 + threadIdx.x;
    if (i >= MN) return;
    float v = 0.f;
    for (int z = 0; z < S; ++z) v += g_part[(size_t)z * MN + i];
    int col = i % N;
    if (b1) v += b1[col];
    if (b2) v += b2[col];
    if (act == 1) v = sigf(v);
    if (accf) C[i] += v; else C[i] = v;
}

// ---------------- attention: e = relu(att_enc + att_dec)@W_att -> softmax over P ----------------
__global__ void k_attn(const float* __restrict__ attenc, const float* __restrict__ attdec,
                       const float* __restrict__ Watt, float* __restrict__ alpha,
                       float* __restrict__ outA, int t)
{
    int b = blockIdx.x, tid = threadIdx.x, lane = tid & 31, warp = tid >> 5;
    __shared__ float sd[ATTn], sw[ATTn], se[Pn];
    __shared__ float sred[8];
    __shared__ float smax, ssum;

    for (int j = tid; j < ATTn; j += 256) {
        sd[j] = attdec[(size_t)b * ATTn + j];
        sw[j] = Watt[j];
    }
    __syncthreads();

    for (int p = warp; p < Pn; p += 8) {
        const float* ae = attenc + ((size_t)b * Pn + p) * ATTn;
        float s = 0.f;
        for (int j = lane; j < ATTn; j += 32) {
            float v = ae[j] + sd[j];
            s = fmaf(fmaxf(v, 0.f), sw[j], s);
        }
        for (int o = 16; o; o >>= 1) s += __shfl_xor_sync(0xffffffffu, s, o);
        if (!lane) se[p] = s;
    }
    __syncthreads();

    float v = (tid < Pn) ? se[tid] : -3.0e38f;
    for (int o = 16; o; o >>= 1) v = fmaxf(v, __shfl_xor_sync(0xffffffffu, v, o));
    if (!lane) sred[warp] = v;
    __syncthreads();
    if (tid == 0) {
        float m = sred[0];
        for (int i = 1; i < 8; ++i) m = fmaxf(m, sred[i]);
        smax = m;
    }
    __syncthreads();

    float e = (tid < Pn) ? expf(se[tid] - smax) : 0.f;
    float s2 = e;
    for (int o = 16; o; o >>= 1) s2 += __shfl_xor_sync(0xffffffffu, s2, o);
    if (!lane) sred[warp] = s2;
    __syncthreads();
    if (tid == 0) {
        float s = 0.f;
        for (int i = 0; i < 8; ++i) s += sred[i];
        ssum = s;
    }
    __syncthreads();

    if (tid < Pn) {
        float a = e / ssum;
        alpha[(size_t)b * Pn + tid] = a;
        int msk = t < g_lendec[b];
        outA[((size_t)b * TMn + t) * Pn + tid] = msk ? a : 0.f;
    }
}

// ---------------- weighted = alpha @ enc_sorted ----------------
__global__ void k_weighted(const float* __restrict__ enc, const float* __restrict__ alpha,
                           float* __restrict__ w)
{
    int b = blockIdx.y;
    int d = blockIdx.x * 256 + threadIdx.x;
    __shared__ float sa[Pn];
    if (threadIdx.x < Pn) sa[threadIdx.x] = alpha[(size_t)b * Pn + threadIdx.x];
    __syncthreads();
    int ob = g_order[b];
    const float* e = enc + (size_t)ob * Pn * ENCn + d;
    float s = 0.f;
#pragma unroll 4
    for (int p = 0; p < Pn; ++p) s = fmaf(e[(size_t)p * ENCn], sa[p], s);
    w[(size_t)b * ENCn + d] = s;
}

// ---------------- x1 = [emb(cap_t), weighted*gate] ----------------
__global__ void k_x1(const float* __restrict__ emb, const float* __restrict__ w,
                     const float* __restrict__ gate, float* __restrict__ x1, int t)
{
    int b = blockIdx.x;
    int cap = g_caps[b * Tn + t];
    const float* e = emb + (size_t)cap * EMBn;
    float* xb = x1 + (size_t)b * (EMBn + ENCn);
    for (int j = threadIdx.x; j < EMBn; j += 256) xb[j] = e[j];
    for (int j = threadIdx.x; j < ENCn; j += 256)
        xb[EMBn + j] = w[(size_t)b * ENCn + j] * gate[(size_t)b * ENCn + j];
}

// ---------------- LSTM cell update (masked) ----------------
__global__ void k_lstm(const float* __restrict__ gates, float* __restrict__ h,
                       float* __restrict__ c, int t)
{
    int b = blockIdx.x;
    if (!(t < g_lendec[b])) return;  // frozen: h,c unchanged
    const float* gb = gates + (size_t)b * 4 * DECn;
    for (int j = threadIdx.x; j < DECn; j += 256) {
        float ig = gb[j], fg = gb[DECn + j], gg = gb[2 * DECn + j], og = gb[3 * DECn + j];
        float cv = c[(size_t)b * DECn + j];
        float cn = sigf(fg) * cv + sigf(ig) * tanhf(gg);
        float hn = sigf(og) * tanhf(cn);
        c[(size_t)b * DECn + j] = cn;
        h[(size_t)b * DECn + j] = hn;
    }
}

// ---------------- host ----------------
static inline void gemm(const float* A, const float* B, float* C, const float* bias,
                        int M, int N, int K, int S, int gatherA, int mode, int t)
{
    dim3 g((N + 63) / 64, M / 64, S);
    k_sgemm<<<g, 256>>>(A, B, C, bias, M, N, K, S, gatherA, mode, t);
}
static inline void reducek(float* C, const float* b1, const float* b2,
                           int MN, int N, int S, int act, int accf)
{
    k_reduce<<<(MN + 255) / 256, 256>>>(C, b1, b2, MN, N, S, act, accf);
}

extern "C" void kernel_launch(void* const* d_in, const int* in_sizes, int n_in,
                              void* d_out, int out_size)
{
    const float* enc  = (const float*)d_in[0];
    const int*   caps = (const int*)  d_in[1];
    const int*   lenc = (const int*)  d_in[2];
    const float* emb  = (const float*)d_in[3];
    const float* Wea = (const float*)d_in[4],  *bea = (const float*)d_in[5];
    const float* Wda = (const float*)d_in[6],  *bda = (const float*)d_in[7];
    const float* Wat = (const float*)d_in[8];  /* b_att: softmax-invariant, unused */
    const float* Wih_= (const float*)d_in[10], *bih_= (const float*)d_in[11];
    const float* Wic = (const float*)d_in[12], *bic = (const float*)d_in[13];
    const float* Wih = (const float*)d_in[14], *bih = (const float*)d_in[15];
    const float* Whh = (const float*)d_in[16], *bhh = (const float*)d_in[17];
    const float* Wfb = (const float*)d_in[18], *bfb = (const float*)d_in[19];
    const float* Wfc = (const float*)d_in[20], *bfc = (const float*)d_in[21];
    float* out = (float*)d_out;

    float* S0 = nullptr;
    cudaGetSymbolAddress((void**)&S0, g_scratch);
    float* attenc = S0 + S_ATTENC;
    float* mu     = S0 + S_MU;
    float* h      = S0 + S_H;
    float* c      = S0 + S_C;
    float* attdec = S0 + S_ATTDEC;
    float* alpha  = S0 + S_ALPHA;
    float* weight = S0 + S_WEIGHT;
    float* gate   = S0 + S_GATE;
    float* x1     = S0 + S_X1;
    float* gates  = S0 + S_GATES;

    // 1. stable sort + caps/len_dec/order outputs
    k_sort<<<1, 128>>>(lenc, caps, out);
    // 2. mu
    k_mu<<<128, 256>>>(enc, mu);
    // 3. init h, c  (split-K)
    gemm(mu, Wih_, nullptr, nullptr, 128, 512, 2048, 8, 0, 0, 0);
    reducek(h, bih_, nullptr, 128 * 512, 512, 8, 0, 0);
    gemm(mu, Wic, nullptr, nullptr, 128, 512, 2048, 8, 0, 0, 0);
    reducek(c, bic, nullptr, 128 * 512, 512, 8, 0, 0);
    // 4. att_enc precompute (gathered rows)
    gemm(enc, Wea, attenc, bea, Bn * Pn, 512, 2048, 1, 1, 0, 0);

    // 5. decode loop
    for (int t = 0; t < TMn; ++t) {
        // att_dec = h @ W_dec_att^T + b
        gemm(h, Wda, nullptr, nullptr, 128, 512, 512, 4, 0, 0, 0);
        reducek(attdec, bda, nullptr, 128 * 512, 512, 4, 0, 0);
        // attention scores + softmax + masked alpha output
        k_attn<<<128, 256>>>(attenc, attdec, Wat, alpha, out + OFF_ALPHA, t);
        // weighted context
        k_weighted<<<dim3(ENCn / 256, 128), 256>>>(enc, alpha, weight);
        // gate = sigmoid(h @ W_fbeta^T + b)
        gemm(h, Wfb, nullptr, nullptr, 128, 2048, 512, 4, 0, 0, 0);
        reducek(gate, bfb, nullptr, 128 * 2048, 2048, 4, 1, 0);
        // x1 = [emb_t, weighted*gate]
        k_x1<<<128, 256>>>(emb, weight, gate, x1, t);
        // gates = x1 @ W_ih^T + b_ih + b_hh
        gemm(x1, Wih, nullptr, nullptr, 128, 2048, 2560, 8, 0, 0, 0);
        reducek(gates, bih, bhh, 128 * 2048, 2048, 8, 0, 0);
        // gates += h @ W_hh^T
        gemm(h, Whh, nullptr, nullptr, 128, 2048, 512, 4, 0, 0, 0);
        reducek(gates, nullptr, nullptr, 128 * 2048, 2048, 4, 0, 1);
        // LSTM update (masked in-place)
        k_lstm<<<128, 256>>>(gates, h, c, t);
        // preds = h @ W_fc^T + b_fc (masked store into output)
        gemm(h, Wfc, out + OFF_PRED, bfc, 128, Vn, 512, 1, 0, 1, t);
    }
}

// round 2
// speedup vs baseline: 1.6927x; 1.6927x over previous
#include <cuda_runtime.h>
#include <math.h>
#include <stdint.h>

// ---------------- problem constants ----------------
#define Bn   128
#define Pn   196
#define ENCn 2048
#define DECn 512
#define Vn   10000
#define Tn   30
#define TMn  29

// ---------------- output layout ----------------
#define OFF_CAPS  0ull
#define OFF_LEN   (128ull*30)
#define OFF_PRED  (OFF_LEN + 128ull)
#define OFF_ALPHA (OFF_PRED + 128ull*29*10000)
#define OFF_ORDER (OFF_ALPHA + 128ull*29*196)

// ---------------- device scratch ----------------
__device__ int   g_order[Bn];
__device__ int   g_lendec[Bn];
__device__ int   g_caps[Bn*Tn];
__device__ int   g_rowmap[Bn*Pn];
__device__ float g_part[4*128*2048];
__device__ float g_scratch[18637312];

// scratch offsets (floats)
#define S_ATTENC 0ull          // 25088*512 = 12845056
#define S_MU     12845056ull   // 128*2048
#define S_H      13107200ull   // 128*512
#define S_C      13172736ull   // 128*512
#define S_ALPHA  13238272ull   // 128*196
#define S_X1     13263360ull   // 128*2560
#define S_HOUT   13591040ull   // 128*4608
#define S_WCOMBO 14180864ull   // 4608*512
#define S_WINIT  16540160ull   // 1024*2048

__device__ __forceinline__ float sigf(float x) { return 1.0f / (1.0f + expf(-x)); }

__device__ __forceinline__ uint32_t f2tf(float x) {
    uint32_t r; asm("cvt.rna.tf32.f32 %0, %1;" : "=r"(r) : "f"(x)); return r;
}

// ---------------- sort (stable counting sort, descending lens) ----------------
__global__ void k_sort(const int* __restrict__ lenc, const int* __restrict__ caps,
                       float* __restrict__ out)
{
    __shared__ int so[Bn];
    int tid = threadIdx.x;
    if (tid == 0) {
        int idx = 0;
        for (int v = Tn; v >= 2; --v)
            for (int b = 0; b < Bn; ++b)
                if (lenc[b] == v) so[idx++] = b;
    }
    __syncthreads();
    int ob = so[tid];
    g_order[tid]  = ob;
    int L = lenc[ob];
    g_lendec[tid] = L - 1;
    out[OFF_LEN   + tid] = (float)(L - 1);
    out[OFF_ORDER + tid] = (float)ob;
    for (int t = 0; t < Tn; ++t) {
        int cv = caps[ob * Tn + t];
        g_caps[tid * Tn + t] = cv;
        out[OFF_CAPS + (size_t)tid * Tn + t] = (float)cv;
    }
    for (int p = 0; p < Pn; ++p)
        g_rowmap[tid * Pn + p] = ob * Pn + p;
}

// ---------------- pack stacked weights ----------------
// Wcombo[4608][512] = [W_dec_att(512); W_fbeta(2048); W_hh(2048)]
// Winit[1024][2048] = [W_init_h(512); W_init_c(512)]
__global__ void k_pack(const float* __restrict__ Wda, const float* __restrict__ Wfb,
                       const float* __restrict__ Whh, const float* __restrict__ Wih_,
                       const float* __restrict__ Wic)
{
    float* wc = g_scratch + S_WCOMBO;
    float* wi = g_scratch + S_WINIT;
    for (unsigned i = blockIdx.x*256u + threadIdx.x; i < 2359296u; i += gridDim.x*256u) {
        float v;
        if (i < 262144u)        v = Wda[i];
        else if (i < 1310720u)  v = Wfb[i - 262144u];
        else                    v = Whh[i - 1310720u];
        wc[i] = v;
    }
    for (unsigned i = blockIdx.x*256u + threadIdx.x; i < 2097152u; i += gridDim.x*256u)
        wi[i] = (i < 1048576u) ? Wih_[i] : Wic[i - 1048576u];
}

// ---------------- mu = mean over P of enc[order[b]] ----------------
__global__ void k_mu(const float* __restrict__ enc, float* __restrict__ mu)
{
    int b = blockIdx.x;
    int ob = g_order[b];
    const float* e = enc + (size_t)ob * Pn * ENCn;
    for (int d = threadIdx.x; d < ENCn; d += blockDim.x) {
        float s = 0.f;
        for (int p = 0; p < Pn; ++p) s += e[(size_t)p * ENCn + d];
        mu[(size_t)b * ENCn + d] = s * (1.0f / 196.0f);
    }
}

// ---------------- tf32 tensor-core GEMM: C[M,N] = A[M,K] @ B[N,K]^T ----------------
// BM=128 BN=64 BK=32, 256 threads (8 warps as 4x2, warp tile 32x32, m16n8k8 atoms)
// cp.async double-buffered; smem stride 36 floats -> conflict-free frag loads.
// S>1: write split-K partials to g_part (no bias). mode 1: masked preds store.
#define GBM 128
#define GBN 64
#define GBK 32
#define SPAD 36

__global__ void __launch_bounds__(256) k_mma(
    const float* __restrict__ A, const float* __restrict__ B,
    float* __restrict__ C, const float* __restrict__ bias,
    int M, int N, int K, int S, int gatherA, int mode, int tstep)
{
    extern __shared__ float sm[];
    const int ASZ = GBM * SPAD;   // 4608 floats
    const int BSZ = GBN * SPAD;   // 2304 floats
    float* As = sm;
    float* Bs = sm + 2*ASZ;

    int tid  = threadIdx.x;
    int lane = tid & 31, wid = tid >> 5;
    int wm = wid & 3, wn = wid >> 2;
    int n0 = blockIdx.x * GBN;
    int m0 = blockIdx.y * GBM;
    int Kc = K / S;
    int k0 = blockIdx.z * Kc;
    int nkt = Kc / GBK;

    // per-thread global->smem load maps (A: 4 float4, B: 2 float4)
    const float* asrc[4]; int adst[4];
#pragma unroll
    for (int q = 0; q < 4; ++q) {
        int f = tid + q*256;
        int r = f >> 3, kq = f & 7;
        int gr = m0 + r;
        if (gatherA) gr = g_rowmap[gr];
        asrc[q] = A + (size_t)gr * K + k0 + kq*4;
        adst[q] = r * SPAD + kq*4;
    }
    const float* bsrc[2]; int bdst[2]; int bsz[2];
#pragma unroll
    for (int q = 0; q < 2; ++q) {
        int f = tid + q*256;
        int r = f >> 3, kq = f & 7;
        int gn = n0 + r;
        bsz[q]  = (gn < N) ? 16 : 0;
        bsrc[q] = B + (size_t)(gn < N ? gn : 0) * K + k0 + kq*4;
        bdst[q] = r * SPAD + kq*4;
    }

    uint32_t smA = (uint32_t)__cvta_generic_to_shared(As);
    uint32_t smB = (uint32_t)__cvta_generic_to_shared(Bs);

    float acc[2][4][4];
#pragma unroll
    for (int i = 0; i < 2; ++i)
#pragma unroll
        for (int j = 0; j < 4; ++j)
#pragma unroll
            for (int v = 0; v < 4; ++v) acc[i][j][v] = 0.f;

    // prefetch tile 0
#pragma unroll
    for (int q = 0; q < 4; ++q)
        asm volatile("cp.async.cg.shared.global [%0], [%1], 16;"
                     :: "r"(smA + adst[q]*4), "l"(asrc[q]));
#pragma unroll
    for (int q = 0; q < 2; ++q)
        asm volatile("cp.async.cg.shared.global [%0], [%1], 16, %2;"
                     :: "r"(smB + bdst[q]*4), "l"(bsrc[q]), "r"(bsz[q]));
    asm volatile("cp.async.commit_group;");

    int buf = 0;
    int rA = lane >> 2, cA = lane & 3;
    for (int kt = 0; kt < nkt; ++kt) {
        asm volatile("cp.async.wait_group 0;");
        __syncthreads();
        if (kt + 1 < nkt) {
            int nb = buf ^ 1;
            uint32_t ab = smA + nb*ASZ*4, bb = smB + nb*BSZ*4;
            int off = (kt + 1) * GBK;
#pragma unroll
            for (int q = 0; q < 4; ++q)
                asm volatile("cp.async.cg.shared.global [%0], [%1], 16;"
                             :: "r"(ab + adst[q]*4), "l"(asrc[q] + off));
#pragma unroll
            for (int q = 0; q < 2; ++q)
                asm volatile("cp.async.cg.shared.global [%0], [%1], 16, %2;"
                             :: "r"(bb + bdst[q]*4), "l"(bsrc[q] + off), "r"(bsz[q]));
            asm volatile("cp.async.commit_group;");
        }
        const float* Ab = As + buf*ASZ;
        const float* Bb = Bs + buf*BSZ;
#pragma unroll
        for (int ka = 0; ka < 4; ++ka) {
            int kk = ka * 8;
            uint32_t a[2][4], b[4][2];
#pragma unroll
            for (int ma = 0; ma < 2; ++ma) {
                int mb = wm*32 + ma*16;
                a[ma][0] = f2tf(Ab[(mb + rA    )*SPAD + kk + cA    ]);
                a[ma][1] = f2tf(Ab[(mb + rA + 8)*SPAD + kk + cA    ]);
                a[ma][2] = f2tf(Ab[(mb + rA    )*SPAD + kk + cA + 4]);
                a[ma][3] = f2tf(Ab[(mb + rA + 8)*SPAD + kk + cA + 4]);
            }
#pragma unroll
            for (int na = 0; na < 4; ++na) {
                int nb2 = wn*32 + na*8;
                b[na][0] = f2tf(Bb[(nb2 + rA)*SPAD + kk + cA    ]);
                b[na][1] = f2tf(Bb[(nb2 + rA)*SPAD + kk + cA + 4]);
            }
#pragma unroll
            for (int ma = 0; ma < 2; ++ma)
#pragma unroll
                for (int na = 0; na < 4; ++na)
                    asm volatile(
                        "mma.sync.aligned.m16n8k8.row.col.f32.tf32.tf32.f32 "
                        "{%0,%1,%2,%3},{%4,%5,%6,%7},{%8,%9},{%0,%1,%2,%3};"
                        : "+f"(acc[ma][na][0]), "+f"(acc[ma][na][1]),
                          "+f"(acc[ma][na][2]), "+f"(acc[ma][na][3])
                        : "r"(a[ma][0]), "r"(a[ma][1]), "r"(a[ma][2]), "r"(a[ma][3]),
                          "r"(b[na][0]), "r"(b[na][1]));
        }
        buf ^= 1;
    }

    // epilogue
    int c2 = (lane & 3) * 2;
#pragma unroll
    for (int ma = 0; ma < 2; ++ma) {
#pragma unroll
        for (int na = 0; na < 4; ++na) {
            int row = m0 + wm*32 + ma*16 + rA;
            int col = n0 + wn*32 + na*8 + c2;
#pragma unroll
            for (int v = 0; v < 4; ++v) {
                int rr = row + (v >> 1) * 8;
                int cc = col + (v & 1);
                if (cc >= N) continue;
                float val = acc[ma][na][v];
                if (S > 1) {
                    g_part[(size_t)blockIdx.z * M * N + (size_t)rr * N + cc] = val;
                } else {
                    if (bias) val += bias[cc];
                    if (mode == 1) {
                        int msk = tstep < g_lendec[rr];
                        C[((size_t)rr * TMn + tstep) * Vn + cc] = msk ? val : 0.f;
                    } else {
                        C[(size_t)rr * N + cc] = val;
                    }
                }
            }
        }
    }
}

// ---------------- split-K reduce for init h,c ----------------
__global__ void k_inithc(const float* __restrict__ bih_, const float* __restrict__ bic)
{
    int i = blockIdx.x*256 + threadIdx.x;   // < 131072 (128 x 1024)
    int row = i >> 10, col = i & 1023;
    float v = g_part[i] + g_part[131072 + i] + g_part[262144 + i] + g_part[393216 + i];
    if (col < 512) g_scratch[S_H + (size_t)row*512 + col]       = v + bih_[col];
    else           g_scratch[S_C + (size_t)row*512 + col - 512] = v + bic[col - 512];
}

// ---------------- attention: e = relu(att_enc + att_dec)@W_att -> softmax ----------------
__global__ void k_attn(const float* __restrict__ attenc, const float* __restrict__ bda,
                       const float* __restrict__ Watt, float* __restrict__ outA, int t)
{
    int b = blockIdx.x, tid = threadIdx.x, lane = tid & 31, warp = tid >> 5;
    __shared__ float sd[512], sw[512], se[Pn];
    __shared__ float sred[8];
    __shared__ float smax, ssum;

    for (int j = tid; j < 512; j += 256) {
        sd[j] = g_scratch[S_HOUT + (size_t)b*4608 + j] + bda[j];
        sw[j] = Watt[j];
    }
    __syncthreads();

    for (int p = warp; p < Pn; p += 8) {
        const float* ae = attenc + ((size_t)b * Pn + p) * 512;
        float s = 0.f;
        for (int j = lane; j < 512; j += 32) {
            float v = ae[j] + sd[j];
            s = fmaf(fmaxf(v, 0.f), sw[j], s);
        }
        for (int o = 16; o; o >>= 1) s += __shfl_xor_sync(0xffffffffu, s, o);
        if (!lane) se[p] = s;
    }
    __syncthreads();

    float v = (tid < Pn) ? se[tid] : -3.0e38f;
    for (int o = 16; o; o >>= 1) v = fmaxf(v, __shfl_xor_sync(0xffffffffu, v, o));
    if (!lane) sred[warp] = v;
    __syncthreads();
    if (tid == 0) {
        float m = sred[0];
        for (int i = 1; i < 8; ++i) m = fmaxf(m, sred[i]);
        smax = m;
    }
    __syncthreads();

    float e = (tid < Pn) ? expf(se[tid] - smax) : 0.f;
    float s2 = e;
    for (int o = 16; o; o >>= 1) s2 += __shfl_xor_sync(0xffffffffu, s2, o);
    if (!lane) sred[warp] = s2;
    __syncthreads();
    if (tid == 0) {
        float s = 0.f;
        for (int i = 0; i < 8; ++i) s += sred[i];
        ssum = s;
    }
    __syncthreads();

    if (tid < Pn) {
        float a = e / ssum;
        g_scratch[S_ALPHA + (size_t)b * Pn + tid] = a;
        int msk = t < g_lendec[b];
        outA[((size_t)b * TMn + t) * Pn + tid] = msk ? a : 0.f;
    }
}

// ---------------- fused: weighted context * gate, emb lookup -> x1 ----------------
__global__ void k_wx(const float* __restrict__ enc, const float* __restrict__ emb,
                     const float* __restrict__ bfb, int t)
{
    int b = blockIdx.y;
    float* x1 = g_scratch + S_X1 + (size_t)b * 2560;
    if (blockIdx.x == 0) {
        int cap = g_caps[b * Tn + t];
        const float* e = emb + (size_t)cap * 512;
        for (int j = threadIdx.x; j < 512; j += 256) x1[j] = e[j];
        return;
    }
    __shared__ float sa[Pn];
    if (threadIdx.x < Pn)
        sa[threadIdx.x] = g_scratch[S_ALPHA + (size_t)b * Pn + threadIdx.x];
    __syncthreads();
    int d = (blockIdx.x - 1) * 256 + threadIdx.x;
    int ob = g_order[b];
    const float* e = enc + (size_t)ob * Pn * ENCn + d;
    float s = 0.f;
#pragma unroll 4
    for (int p = 0; p < Pn; ++p) s = fmaf(e[(size_t)p * ENCn], sa[p], s);
    float gp = g_scratch[S_HOUT + (size_t)b*4608 + 512 + d] + bfb[d];
    x1[512 + d] = s * sigf(gp);
}

// ---------------- LSTM: reduce 4 split-K partials + biases + hh, activations ----------------
__global__ void k_lstm(const float* __restrict__ bih, const float* __restrict__ bhh, int t)
{
    int b = blockIdx.x;
    if (!(t < g_lendec[b])) return;
    int j = threadIdx.x;  // 512 threads
    float g[4];
#pragma unroll
    for (int q = 0; q < 4; ++q) {
        int col = q * 512 + j;
        size_t idx = (size_t)b * 2048 + col;
        float v = g_part[idx] + g_part[262144 + idx] + g_part[524288 + idx] + g_part[786432 + idx];
        v += bih[col] + bhh[col] + g_scratch[S_HOUT + (size_t)b*4608 + 2560 + col];
        g[q] = v;
    }
    float* h = g_scratch + S_H + (size_t)b * 512;
    float* c = g_scratch + S_C + (size_t)b * 512;
    float cn = sigf(g[1]) * c[j] + sigf(g[0]) * tanhf(g[2]);
    float hn = sigf(g[3]) * tanhf(cn);
    c[j] = cn;
    h[j] = hn;
}

// ---------------- host ----------------
static inline void mma_gemm(const float* A, const float* B, float* C, const float* bias,
                            int M, int N, int K, int S, int gather, int mode, int t)
{
    dim3 g((N + GBN - 1) / GBN, M / GBM, S);
    k_mma<<<g, 256, 55296>>>(A, B, C, bias, M, N, K, S, gather, mode, t);
}

extern "C" void kernel_launch(void* const* d_in, const int* in_sizes, int n_in,
                              void* d_out, int out_size)
{
    const float* enc  = (const float*)d_in[0];
    const int*   caps = (const int*)  d_in[1];
    const int*   lenc = (const int*)  d_in[2];
    const float* emb  = (const float*)d_in[3];
    const float* Wea = (const float*)d_in[4],  *bea = (const float*)d_in[5];
    const float* Wda = (const float*)d_in[6],  *bda = (const float*)d_in[7];
    const float* Wat = (const float*)d_in[8];  /* d_in[9]=b_att: softmax-invariant */
    const float* Wih_= (const float*)d_in[10], *bih_= (const float*)d_in[11];
    const float* Wic = (const float*)d_in[12], *bic = (const float*)d_in[13];
    const float* Wih = (const float*)d_in[14], *bih = (const float*)d_in[15];
    const float* Whh = (const float*)d_in[16], *bhh = (const float*)d_in[17];
    const float* Wfb = (const float*)d_in[18], *bfb = (const float*)d_in[19];
    const float* Wfc = (const float*)d_in[20], *bfc = (const float*)d_in[21];
    float* out = (float*)d_out;

    cudaFuncSetAttribute(k_mma, cudaFuncAttributeMaxDynamicSharedMemorySize, 55296);

    float* S0 = nullptr;
    cudaGetSymbolAddress((void**)&S0, g_scratch);
    float* attenc = S0 + S_ATTENC;
    float* mu     = S0 + S_MU;
    float* h      = S0 + S_H;
    float* x1     = S0 + S_X1;
    float* hout   = S0 + S_HOUT;
    float* wcombo = S0 + S_WCOMBO;
    float* winit  = S0 + S_WINIT;

    // init
    k_sort<<<1, 128>>>(lenc, caps, out);
    k_pack<<<2048, 256>>>(Wda, Wfb, Whh, Wih_, Wic);
    k_mu<<<128, 256>>>(enc, mu);
    // h,c init: [h;c] = mu @ [W_init_h; W_init_c]^T  (split-K 4)
    mma_gemm(mu, winit, nullptr, nullptr, 128, 1024, 2048, 4, 0, 0, 0);
    k_inithc<<<512, 256>>>(bih_, bic);
    // att_enc precompute (gathered rows): 25088 x 512 x 2048
    mma_gemm(enc, Wea, attenc, bea, Bn * Pn, 512, 2048, 1, 1, 0, 0);

    // decode loop
    for (int t = 0; t < TMn; ++t) {
        // Hout = h @ [W_dec_att; W_fbeta; W_hh]^T  (128 x 4608 x 512)
        mma_gemm(h, wcombo, hout, nullptr, 128, 4608, 512, 1, 0, 0, 0);
        // attention + softmax + masked alpha output
        k_attn<<<128, 256>>>(attenc, bda, Wat, out + OFF_ALPHA, t);
        // x1 = [emb_t, (alpha @ enc) * sigmoid(gate_pre + bfb)]
        k_wx<<<dim3(9, 128), 256>>>(enc, emb, bfb, t);
        // gates partials = x1 @ W_ih^T  (128 x 2048 x 2560, split-K 4)
        mma_gemm(x1, Wih, nullptr, nullptr, 128, 2048, 2560, 4, 0, 0, 0);
        // LSTM: reduce partials + b_ih + b_hh + hh_part, activations, masked h/c update
        k_lstm<<<128, 512>>>(bih, bhh, t);
        // preds = h @ W_fc^T + b_fc (masked store)
        mma_gemm(h, Wfc, out + OFF_PRED, bfc, 128, Vn, 512, 1, 0, 1, t);
    }
}

// round 3
// speedup vs baseline: 2.0190x; 1.1928x over previous
#include <cuda_runtime.h>
#include <math.h>
#include <stdint.h>

// ---------------- problem constants ----------------
#define Bn   128
#define Pn   196
#define ENCn 2048
#define DECn 512
#define Vn   10000
#define Tn   30
#define TMn  29

// ---------------- output layout ----------------
#define OFF_CAPS  0ull
#define OFF_LEN   (128ull*30)
#define OFF_PRED  (OFF_LEN + 128ull)
#define OFF_ALPHA (OFF_PRED + 128ull*29*10000)
#define OFF_ORDER (OFF_ALPHA + 128ull*29*196)

// ---------------- device scratch ----------------
__device__ int   g_order[Bn];
__device__ int   g_lendec[Bn];
__device__ int   g_act[TMn];
__device__ int   g_caps[Bn*Tn];
__device__ int   g_rowmap[Bn*Pn];
__device__ float g_part[4*128*2048];
__device__ float g_scratch[18637312];

// scratch offsets (floats)
#define S_ATTENC 0ull          // 25088*512 = 12845056
#define S_MU     12845056ull   // 128*2048
#define S_H      13107200ull   // 128*512
#define S_C      13172736ull   // 128*512
#define S_ALPHA  13238272ull   // 128*196
#define S_X1     13263360ull   // 128*2560
#define S_HOUT   13591040ull   // 128*4608
#define S_WCOMBO 14180864ull   // 4608*512
#define S_WINIT  16540160ull   // 1024*2048

__device__ __forceinline__ float sigf(float x) { return 1.0f / (1.0f + expf(-x)); }
__device__ __forceinline__ uint32_t f2tf(float x) {
    uint32_t r; asm("cvt.rna.tf32.f32 %0, %1;" : "=r"(r) : "f"(x)); return r;
}

// ---------------- sort (stable counting sort, descending lens) + act counts ----------
__global__ void k_sort(const int* __restrict__ lenc, const int* __restrict__ caps,
                       float* __restrict__ out)
{
    __shared__ int so[Bn];
    int tid = threadIdx.x;
    if (tid == 0) {
        int idx = 0;
        for (int v = Tn; v >= 2; --v)
            for (int b = 0; b < Bn; ++b)
                if (lenc[b] == v) so[idx++] = b;
    }
    __syncthreads();
    int ob = so[tid];
    g_order[tid]  = ob;
    int L = lenc[ob];
    g_lendec[tid] = L - 1;
    out[OFF_LEN   + tid] = (float)(L - 1);
    out[OFF_ORDER + tid] = (float)ob;
    for (int t = 0; t < Tn; ++t) {
        int cv = caps[ob * Tn + t];
        g_caps[tid * Tn + t] = cv;
        out[OFF_CAPS + (size_t)tid * Tn + t] = (float)cv;
    }
    for (int p = 0; p < Pn; ++p)
        g_rowmap[tid * Pn + p] = ob * Pn + p;
    __syncthreads();
    if (tid < TMn) {
        int cnt = 0;
        for (int b = 0; b < Bn; ++b) cnt += (g_lendec[b] > tid) ? 1 : 0;
        g_act[tid] = cnt;
    }
}

// ---------------- pack stacked weights ----------------
__global__ void k_pack(const float* __restrict__ Wda, const float* __restrict__ Wfb,
                       const float* __restrict__ Whh, const float* __restrict__ Wih_,
                       const float* __restrict__ Wic)
{
    float* wc = g_scratch + S_WCOMBO;
    float* wi = g_scratch + S_WINIT;
    for (unsigned i = blockIdx.x*256u + threadIdx.x; i < 2359296u; i += gridDim.x*256u) {
        float v;
        if (i < 262144u)        v = Wda[i];
        else if (i < 1310720u)  v = Wfb[i - 262144u];
        else                    v = Whh[i - 1310720u];
        wc[i] = v;
    }
    for (unsigned i = blockIdx.x*256u + threadIdx.x; i < 2097152u; i += gridDim.x*256u)
        wi[i] = (i < 1048576u) ? Wih_[i] : Wic[i - 1048576u];
}

// ---------------- mu = mean over P of enc[order[b]] ----------------
__global__ void k_mu(const float* __restrict__ enc, float* __restrict__ mu)
{
    int b = blockIdx.x;
    int ob = g_order[b];
    const float* e = enc + (size_t)ob * Pn * ENCn;
    for (int d = threadIdx.x; d < ENCn; d += blockDim.x) {
        float s = 0.f;
        for (int p = 0; p < Pn; ++p) s += e[(size_t)p * ENCn + d];
        mu[(size_t)b * ENCn + d] = s * (1.0f / 196.0f);
    }
}

// ---------------- tf32 tensor-core GEMM: C[M,N] = A[M,K] @ B[N,K]^T ----------------
// BM=64 BN=64 BK=32, 256 thr (8 warps 4x2, warp tile 16x32), 4-stage cp.async.
// actp: active-row prefix; blocks with m0>=act skip (mode 1: write zeros).
#define GBM 64
#define GBN 64
#define GBK 32
#define SPAD 36
#define ASZf (GBM*SPAD)            // 2304 floats
#define STGf (2*ASZf)              // 4608 floats per stage (A then B)
#define SMEMB (4*STGf*4)           // 73728 bytes

__global__ void __launch_bounds__(256) k_mma(
    const float* __restrict__ A, const float* __restrict__ B,
    float* __restrict__ C, const float* __restrict__ bias,
    int M, int N, int K, int S, int gatherA, int mode, int tstep,
    const int* __restrict__ actp)
{
    extern __shared__ float sm[];
    int tid  = threadIdx.x;
    int lane = tid & 31, wid = tid >> 5;
    int wm = wid & 3, wn = wid >> 2;
    int n0 = blockIdx.x * GBN;
    int m0 = blockIdx.y * GBM;

    int act = actp ? *actp : M;
    if (m0 >= act) {
        if (mode == 1) {
            for (int i = tid; i < GBM*GBN; i += 256) {
                int rr = m0 + (i >> 6), cc = n0 + (i & 63);
                if (rr < M && cc < N)
                    C[((size_t)rr * TMn + tstep) * Vn + cc] = 0.f;
            }
        }
        return;
    }

    int Kc = K / S;
    int k0 = blockIdx.z * Kc;
    int nkt = Kc / GBK;

    // per-thread load maps (A: 2 float4, B: 2 float4 per stage)
    const float* asrc[2]; uint32_t adst[2];
#pragma unroll
    for (int q = 0; q < 2; ++q) {
        int f = tid + q*256;
        int r = f >> 3, kq = f & 7;
        int gr = m0 + r;
        if (gatherA) gr = g_rowmap[gr];
        asrc[q] = A + (size_t)gr * K + k0 + kq*4;
        adst[q] = (r * SPAD + kq*4) * 4;
    }
    const float* bsrc[2]; uint32_t bdst[2]; int bsz[2];
#pragma unroll
    for (int q = 0; q < 2; ++q) {
        int f = tid + q*256;
        int r = f >> 3, kq = f & 7;
        int gn = n0 + r;
        bsz[q]  = (gn < N) ? 16 : 0;
        bsrc[q] = B + (size_t)(gn < N ? gn : 0) * K + k0 + kq*4;
        bdst[q] = (ASZf + r * SPAD + kq*4) * 4;
    }

    uint32_t smb = (uint32_t)__cvta_generic_to_shared(sm);

    float acc[4][4];
#pragma unroll
    for (int j = 0; j < 4; ++j)
#pragma unroll
        for (int v = 0; v < 4; ++v) acc[j][v] = 0.f;

    // prologue: prefetch stages 0..2
#pragma unroll
    for (int s = 0; s < 3; ++s) {
        if (s < nkt) {
            uint32_t sb = smb + s * STGf * 4;
            int off = s * GBK;
#pragma unroll
            for (int q = 0; q < 2; ++q)
                asm volatile("cp.async.cg.shared.global [%0], [%1], 16;"
                             :: "r"(sb + adst[q]), "l"(asrc[q] + off));
#pragma unroll
            for (int q = 0; q < 2; ++q)
                asm volatile("cp.async.cg.shared.global [%0], [%1], 16, %2;"
                             :: "r"(sb + bdst[q]), "l"(bsrc[q] + off), "r"(bsz[q]));
        }
        asm volatile("cp.async.commit_group;");
    }

    int rA = lane >> 2, cA = lane & 3;
    for (int kt = 0; kt < nkt; ++kt) {
        asm volatile("cp.async.wait_group 2;");
        __syncthreads();
        // prefetch stage kt+3
        {
            int s = kt + 3;
            if (s < nkt) {
                uint32_t sb = smb + (s & 3) * STGf * 4;
                int off = s * GBK;
#pragma unroll
                for (int q = 0; q < 2; ++q)
                    asm volatile("cp.async.cg.shared.global [%0], [%1], 16;"
                                 :: "r"(sb + adst[q]), "l"(asrc[q] + off));
#pragma unroll
                for (int q = 0; q < 2; ++q)
                    asm volatile("cp.async.cg.shared.global [%0], [%1], 16, %2;"
                                 :: "r"(sb + bdst[q]), "l"(bsrc[q] + off), "r"(bsz[q]));
            }
            asm volatile("cp.async.commit_group;");
        }
        const float* Ab = sm + (kt & 3) * STGf;
        const float* Bb = Ab + ASZf;
#pragma unroll
        for (int ka = 0; ka < 4; ++ka) {
            int kk = ka * 8;
            uint32_t a[4], b[4][2];
            {
                int mb = wm * 16;
                a[0] = f2tf(Ab[(mb + rA    )*SPAD + kk + cA    ]);
                a[1] = f2tf(Ab[(mb + rA + 8)*SPAD + kk + cA    ]);
                a[2] = f2tf(Ab[(mb + rA    )*SPAD + kk + cA + 4]);
                a[3] = f2tf(Ab[(mb + rA + 8)*SPAD + kk + cA + 4]);
            }
#pragma unroll
            for (int na = 0; na < 4; ++na) {
                int nb2 = wn*32 + na*8;
                b[na][0] = f2tf(Bb[(nb2 + rA)*SPAD + kk + cA    ]);
                b[na][1] = f2tf(Bb[(nb2 + rA)*SPAD + kk + cA + 4]);
            }
#pragma unroll
            for (int na = 0; na < 4; ++na)
                asm volatile(
                    "mma.sync.aligned.m16n8k8.row.col.f32.tf32.tf32.f32 "
                    "{%0,%1,%2,%3},{%4,%5,%6,%7},{%8,%9},{%0,%1,%2,%3};"
                    : "+f"(acc[na][0]), "+f"(acc[na][1]),
                      "+f"(acc[na][2]), "+f"(acc[na][3])
                    : "r"(a[0]), "r"(a[1]), "r"(a[2]), "r"(a[3]),
                      "r"(b[na][0]), "r"(b[na][1]));
        }
    }

    // epilogue
    int c2 = (lane & 3) * 2;
#pragma unroll
    for (int na = 0; na < 4; ++na) {
        int row = m0 + wm*16 + rA;
        int col = n0 + wn*32 + na*8 + c2;
#pragma unroll
        for (int v = 0; v < 4; ++v) {
            int rr = row + (v >> 1) * 8;
            int cc = col + (v & 1);
            if (cc >= N || rr >= M) continue;
            float val = acc[na][v];
            if (S > 1) {
                g_part[(size_t)blockIdx.z * M * N + (size_t)rr * N + cc] = val;
            } else {
                if (bias) val += bias[cc];
                if (mode == 1) {
                    int msk = tstep < g_lendec[rr];
                    C[((size_t)rr * TMn + tstep) * Vn + cc] = msk ? val : 0.f;
                } else {
                    C[(size_t)rr * N + cc] = val;
                }
            }
        }
    }
}

// ---------------- split-K reduce for init h,c ----------------
__global__ void k_inithc(const float* __restrict__ bih_, const float* __restrict__ bic)
{
    int i = blockIdx.x*256 + threadIdx.x;
    int row = i >> 10, col = i & 1023;
    float v = g_part[i] + g_part[131072 + i] + g_part[262144 + i] + g_part[393216 + i];
    if (col < 512) g_scratch[S_H + (size_t)row*512 + col]       = v + bih_[col];
    else           g_scratch[S_C + (size_t)row*512 + col - 512] = v + bic[col - 512];
}

// ---------------- attention ----------------
__global__ void k_attn(const float* __restrict__ attenc, const float* __restrict__ bda,
                       const float* __restrict__ Watt, float* __restrict__ outA, int t)
{
    int b = blockIdx.x, tid = threadIdx.x, lane = tid & 31, warp = tid >> 5;
    if (!(t < g_lendec[b])) {   // masked row: zero alpha output, skip all work
        for (int j = tid; j < Pn; j += 256)
            outA[((size_t)b * TMn + t) * Pn + j] = 0.f;
        return;
    }
    __shared__ float sd[512], sw[512], se[Pn];
    __shared__ float sred[8];
    __shared__ float smax, ssum;

    for (int j = tid; j < 512; j += 256) {
        sd[j] = g_scratch[S_HOUT + (size_t)b*4608 + j] + bda[j];
        sw[j] = Watt[j];
    }
    __syncthreads();

    for (int p = warp; p < Pn; p += 8) {
        const float* ae = attenc + ((size_t)b * Pn + p) * 512;
        float s = 0.f;
        for (int j = lane; j < 512; j += 32) {
            float v = ae[j] + sd[j];
            s = fmaf(fmaxf(v, 0.f), sw[j], s);
        }
        for (int o = 16; o; o >>= 1) s += __shfl_xor_sync(0xffffffffu, s, o);
        if (!lane) se[p] = s;
    }
    __syncthreads();

    float v = (tid < Pn) ? se[tid] : -3.0e38f;
    for (int o = 16; o; o >>= 1) v = fmaxf(v, __shfl_xor_sync(0xffffffffu, v, o));
    if (!lane) sred[warp] = v;
    __syncthreads();
    if (tid == 0) {
        float m = sred[0];
        for (int i = 1; i < 8; ++i) m = fmaxf(m, sred[i]);
        smax = m;
    }
    __syncthreads();

    float e = (tid < Pn) ? expf(se[tid] - smax) : 0.f;
    float s2 = e;
    for (int o = 16; o; o >>= 1) s2 += __shfl_xor_sync(0xffffffffu, s2, o);
    if (!lane) sred[warp] = s2;
    __syncthreads();
    if (tid == 0) {
        float s = 0.f;
        for (int i = 0; i < 8; ++i) s += sred[i];
        ssum = s;
    }
    __syncthreads();

    if (tid < Pn) {
        float a = e / ssum;
        g_scratch[S_ALPHA + (size_t)b * Pn + tid] = a;
        outA[((size_t)b * TMn + t) * Pn + tid] = a;
    }
}

// ---------------- fused: weighted context * gate, emb lookup -> x1 ----------------
__global__ void k_wx(const float* __restrict__ enc, const float* __restrict__ emb,
                     const float* __restrict__ bfb, int t)
{
    int b = blockIdx.y;
    if (!(t < g_lendec[b])) return;   // masked row: x1 stale, never consumed
    float* x1 = g_scratch + S_X1 + (size_t)b * 2560;
    if (blockIdx.x == 0) {
        int cap = g_caps[b * Tn + t];
        const float* e = emb + (size_t)cap * 512;
        for (int j = threadIdx.x; j < 512; j += 256) x1[j] = e[j];
        return;
    }
    __shared__ float sa[Pn];
    if (threadIdx.x < Pn)
        sa[threadIdx.x] = g_scratch[S_ALPHA + (size_t)b * Pn + threadIdx.x];
    __syncthreads();
    int d = (blockIdx.x - 1) * 256 + threadIdx.x;
    int ob = g_order[b];
    const float* e = enc + (size_t)ob * Pn * ENCn + d;
    float s = 0.f;
#pragma unroll 8
    for (int p = 0; p < Pn; ++p) s = fmaf(e[(size_t)p * ENCn], sa[p], s);
    float gp = g_scratch[S_HOUT + (size_t)b*4608 + 512 + d] + bfb[d];
    x1[512 + d] = s * sigf(gp);
}

// ---------------- LSTM ----------------
__global__ void k_lstm(const float* __restrict__ bih, const float* __restrict__ bhh, int t)
{
    int b = blockIdx.x;
    if (!(t < g_lendec[b])) return;
    int j = threadIdx.x;
    float g[4];
#pragma unroll
    for (int q = 0; q < 4; ++q) {
        int col = q * 512 + j;
        size_t idx = (size_t)b * 2048 + col;
        float v = g_part[idx] + g_part[262144 + idx] + g_part[524288 + idx] + g_part[786432 + idx];
        v += bih[col] + bhh[col] + g_scratch[S_HOUT + (size_t)b*4608 + 2560 + col];
        g[q] = v;
    }
    float* h = g_scratch + S_H + (size_t)b * 512;
    float* c = g_scratch + S_C + (size_t)b * 512;
    float cn = sigf(g[1]) * c[j] + sigf(g[0]) * tanhf(g[2]);
    float hn = sigf(g[3]) * tanhf(cn);
    c[j] = cn;
    h[j] = hn;
}

// ---------------- host ----------------
static inline void mma_gemm(const float* A, const float* B, float* C, const float* bias,
                            int M, int N, int K, int S, int gather, int mode, int t,
                            const int* actp)
{
    dim3 g((N + GBN - 1) / GBN, (M + GBM - 1) / GBM, S);
    k_mma<<<g, 256, SMEMB>>>(A, B, C, bias, M, N, K, S, gather, mode, t, actp);
}

extern "C" void kernel_launch(void* const* d_in, const int* in_sizes, int n_in,
                              void* d_out, int out_size)
{
    const float* enc  = (const float*)d_in[0];
    const int*   caps = (const int*)  d_in[1];
    const int*   lenc = (const int*)  d_in[2];
    const float* emb  = (const float*)d_in[3];
    const float* Wea = (const float*)d_in[4],  *bea = (const float*)d_in[5];
    const float* bda = (const float*)d_in[7];
    const float* Wat = (const float*)d_in[8];
    const float* bih_= (const float*)d_in[11];
    const float* bic = (const float*)d_in[13];
    const float* Wih = (const float*)d_in[14], *bih = (const float*)d_in[15];
    const float* bhh = (const float*)d_in[17];
    const float* bfb = (const float*)d_in[19];
    const float* Wfc = (const float*)d_in[20], *bfc = (const float*)d_in[21];
    float* out = (float*)d_out;

    cudaFuncSetAttribute(k_mma, cudaFuncAttributeMaxDynamicSharedMemorySize, SMEMB);

    float* S0 = nullptr;
    cudaGetSymbolAddress((void**)&S0, g_scratch);
    int* actd = nullptr;
    cudaGetSymbolAddress((void**)&actd, g_act);
    float* attenc = S0 + S_ATTENC;
    float* mu     = S0 + S_MU;
    float* h      = S0 + S_H;
    float* x1     = S0 + S_X1;
    float* hout   = S0 + S_HOUT;
    float* wcombo = S0 + S_WCOMBO;
    float* winit  = S0 + S_WINIT;

    // init
    k_sort<<<1, 128>>>(lenc, caps, out);
    k_pack<<<2048, 256>>>((const float*)d_in[6], (const float*)d_in[18],
                          (const float*)d_in[16], (const float*)d_in[10],
                          (const float*)d_in[12]);
    k_mu<<<128, 256>>>(enc, mu);
    mma_gemm(mu, winit, nullptr, nullptr, 128, 1024, 2048, 4, 0, 0, 0, nullptr);
    k_inithc<<<512, 256>>>(bih_, bic);
    mma_gemm(enc, Wea, attenc, bea, Bn * Pn, 512, 2048, 1, 1, 0, 0, nullptr);

    // decode loop
    for (int t = 0; t < TMn; ++t) {
        const int* ap = actd + t;
        mma_gemm(h, wcombo, hout, nullptr, 128, 4608, 512, 1, 0, 0, 0, ap);
        k_attn<<<128, 256>>>(attenc, bda, Wat, out + OFF_ALPHA, t);
        k_wx<<<dim3(9, 128), 256>>>(enc, emb, bfb, t);
        mma_gemm(x1, Wih, nullptr, nullptr, 128, 2048, 2560, 4, 0, 0, 0, ap);
        k_lstm<<<128, 512>>>(bih, bhh, t);
        mma_gemm(h, Wfc, out + OFF_PRED, bfc, 128, Vn, 512, 1, 0, 1, t, ap);
    }
}